// round 1
// baseline (speedup 1.0000x reference)
#include <cuda_runtime.h>

// Fused depthwise 1D conv: (5-tap FD 2nd-deriv) o (9-tap Gaussian) == one 13-tap
// valid correlation per row. x: [32 rows, T=1048576] fp32 -> out: [32, T-12].

#define T_LEN 1048576
#define L_OUT (T_LEN - 12)          // 1048564
#define SEG 16                      // outputs per thread
#define SEGS_PER_ROW (T_LEN / SEG)  // 65536 segments (last one partially used)
#define N_ROWS 32

__global__ __launch_bounds__(256)
void fused_conv13_kernel(const float* __restrict__ x,
                         const float* __restrict__ fd,
                         const float* __restrict__ gs,
                         float* __restrict__ out)
{
    __shared__ float c_sh[13];
    const int tid = threadIdx.x;

    // Build combined 13-tap kernel once per block: c[k] = sum_{i+j=k} fd[i]*gs[j]
    if (tid < 13) {
        float acc = 0.f;
        #pragma unroll
        for (int i = 0; i < 5; ++i) {
            int j = tid - i;
            if (j >= 0 && j < 9) acc += fd[i] * gs[j];
        }
        c_sh[tid] = acc;
    }
    __syncthreads();

    float cc[13];
    #pragma unroll
    for (int k = 0; k < 13; ++k) cc[k] = c_sh[k];

    const unsigned sg  = blockIdx.x * blockDim.x + tid;   // global segment id
    const unsigned row = sg >> 16;                        // 65536 segs per row
    const unsigned seg = sg & 65535u;
    const unsigned t0  = seg * SEG;

    const float* __restrict__ xr = x   + (size_t)row * T_LEN;
    float*       __restrict__ orow = out + (size_t)row * L_OUT;

    // Sliding window: 28 inputs cover 16 outputs of a 13-tap filter.
    float xin[28];
    #pragma unroll
    for (int i = 0; i < 7; ++i) {
        const unsigned p = t0 + i * 4u;
        float4 v;
        if (p < T_LEN) {                 // aligned & T%4==0 -> full chunk valid
            v = *reinterpret_cast<const float4*>(xr + p);
        } else {
            v = make_float4(0.f, 0.f, 0.f, 0.f);
        }
        xin[i*4+0] = v.x; xin[i*4+1] = v.y; xin[i*4+2] = v.z; xin[i*4+3] = v.w;
    }

    #pragma unroll
    for (int j = 0; j < 4; ++j) {
        const unsigned p = t0 + j * 4u;
        if (p < L_OUT) {                 // L_OUT%4==0 -> chunk fully valid
            float a0 = 0.f, a1 = 0.f, a2 = 0.f, a3 = 0.f;
            #pragma unroll
            for (int k = 0; k < 13; ++k) {
                const float ck = cc[k];
                a0 = fmaf(ck, xin[j*4 + 0 + k], a0);
                a1 = fmaf(ck, xin[j*4 + 1 + k], a1);
                a2 = fmaf(ck, xin[j*4 + 2 + k], a2);
                a3 = fmaf(ck, xin[j*4 + 3 + k], a3);
            }
            float4 r; r.x = a0; r.y = a1; r.z = a2; r.w = a3;
            *reinterpret_cast<float4*>(orow + p) = r;
        }
    }
}

extern "C" void kernel_launch(void* const* d_in, const int* in_sizes, int n_in,
                              void* d_out, int out_size)
{
    const float* x  = (const float*)d_in[0];   // [8,4,1048576]
    const float* fd = (const float*)d_in[1];   // [5]
    const float* gs = (const float*)d_in[2];   // [9]
    float* out = (float*)d_out;                // [8,4,1048564]

    const int threads = 256;
    const int total_segs = N_ROWS * SEGS_PER_ROW;      // 32 * 65536
    const int blocks = total_segs / threads;           // 8192

    fused_conv13_kernel<<<blocks, threads>>>(x, fd, gs, out);
}